// round 16
// baseline (speedup 1.0000x reference)
#include <cuda_runtime.h>
#include <cuda_fp16.h>
#include <mma.h>
#include <cuda_pipeline.h>
#include <cstdint>

using namespace nvcuda;

// Problem dims
#define M_TOT 8192          // 4*2048
#define N_TOT 14336
#define K_TOT 4096
#define NPACK (N_TOT * (K_TOT / 2))

// GEMM tiling (fp16 wmma 16x16x16, single K pass)
#define BM 128
#define BN 128
#define BK 64               // 64 fp16 per stage row (128B)
#define LDT 72              // smem row stride (halves): 64 + 8 pad (16B-aligned rows)
#define NT (K_TOT / BK)     // 64 k-iterations
#define STAGES 3
#define STAGE_HALVES ((BM + BN) * LDT)              // 18432 halves = 36864 B
#define SMEM_BYTES (STAGES * STAGE_HALVES * 2)      // 110592 B dynamic (2 CTAs/SM)
#define NTHREADS 128        // 4 warps, warp tile 64x64 (2x2)

// Rasterization: supertiles of GROUP_M m-tiles (fast) x all n-tiles
#define TILES_M (M_TOT / BM)      // 64
#define TILES_N (N_TOT / BN)      // 112
#define GROUP_M 16

// Fused prep kernel geometry
#define VEC_A ((M_TOT * K_TOT) / 8)     // 4194304 conv items (8 floats each)
#define VEC_W (NPACK / 4)               // 7340032 unpack items (4 bytes each)
#define A_BLOCKS (VEC_A / 256)          // 16384
#define W_BLOCKS (VEC_W / 256)          // 28672
#define PREP_GRID (1 + A_BLOCKS + W_BLOCKS)

// Scratch (static device globals: allocation-free per harness rules)
__device__ __align__(256) __half g_Ah[(size_t)M_TOT * K_TOT];   // 67 MB: x in fp16
__device__ __align__(256) __half g_Qh[(size_t)N_TOT * K_TOT];   // 117 MB: weights fp16
__device__ int g_swap_sb;   // 1 => sb0 is actually bias

// ---------------------------------------------------------------------------
// Fused prep:
//  block 0:                 sign probe (scale strictly positive vs bias).
//  blocks [1, 1+A_BLOCKS):  x fp32 -> fp16, 8 floats -> one 16B store.
//  remaining blocks:        unpack 4-bit pairs -> fp16 in [-8,7]; each block
//                           self-detects int32-promoted qweight storage by
//                           checking the first 64 words (all in [-128,127]
//                           => promoted; impossible for packed nibble data).
// ---------------------------------------------------------------------------
__device__ __forceinline__ __half2 dec_pair(int v) {
    int hi = v >> 4;                   // arithmetic shift: even column
    int lo = ((v & 15) ^ 8) - 8;       // sign-extended low nibble: odd column
    return __floats2half2_rn((float)hi, (float)lo);
}

__global__ __launch_bounds__(256) void prep_kernel(const float* __restrict__ x,
                                                   const void* __restrict__ qw_raw,
                                                   const float* __restrict__ sb0) {
    const int bid = blockIdx.x;
    const int tid = threadIdx.x;

    if (bid == 0) {
        // Sign probe on sb0: any negative => sb0 is bias.
        int local_neg = 0;
        for (int i = tid; i < N_TOT; i += 256)
            if (sb0[i] < 0.0f) local_neg = 1;
        int any_neg = __syncthreads_or(local_neg);
        if (tid == 0) g_swap_sb = any_neg;
        return;
    }

    if (bid <= A_BLOCKS) {
        // conv_x: idx over groups of 8 floats
        int idx = (bid - 1) * 256 + tid;
        const float4* xv = (const float4*)x;
        float4 a = xv[idx * 2];
        float4 b = xv[idx * 2 + 1];
        union { __half2 h2[4]; uint4 u; } o;
        o.h2[0] = __floats2half2_rn(a.x, a.y);
        o.h2[1] = __floats2half2_rn(a.z, a.w);
        o.h2[2] = __floats2half2_rn(b.x, b.y);
        o.h2[3] = __floats2half2_rn(b.z, b.w);
        ((uint4*)g_Ah)[idx] = o.u;
        return;
    }

    // unpack: block-local dtype probe (words 0..63 are L2-hot across blocks)
    const int* qw32 = (const int*)qw_raw;
    int w0 = qw32[tid & 63];
    int bad = (w0 < -128 || w0 > 127) ? 1 : 0;
    int is_i32 = !__syncthreads_or(bad);

    int idx = (bid - 1 - A_BLOCKS) * 256 + tid;   // per 4 packed bytes
    int b0, b1, b2, b3;
    if (is_i32) {
        int4 w = ((const int4*)qw_raw)[idx];
        b0 = w.x; b1 = w.y; b2 = w.z; b3 = w.w;
    } else {
        int w = qw32[idx];
        b0 = (int)(signed char)(w);
        b1 = (int)(signed char)(w >> 8);
        b2 = (int)(signed char)(w >> 16);
        b3 = (int)(signed char)(w >> 24);
    }
    union { __half2 h2[4]; uint4 u; } o;
    o.h2[0] = dec_pair(b0);
    o.h2[1] = dec_pair(b1);
    o.h2[2] = dec_pair(b2);
    o.h2[3] = dec_pair(b3);
    ((uint4*)g_Qh)[idx] = o.u;
}

// ---------------------------------------------------------------------------
// GEMM: out[m,n] = scale[n] * sum_k Ah[m,k]*Qh[n,k] + bias[n]
// 128x128 CTA tile, 4 warps, warp tile 64x64. BK=64, 3-stage cp.async
// (2 CTAs/SM). LDSMs first each kk, cp.asyncs spread across kks, hoisted
// pointers. float4 epilogue.
// ---------------------------------------------------------------------------
__global__ __launch_bounds__(NTHREADS) void gemm_f16_kernel(const float* __restrict__ sb0,
                                                            const float* __restrict__ sb1,
                                                            float* __restrict__ out) {
    extern __shared__ __align__(16) char dsm[];
    __half* smem_h = reinterpret_cast<__half*>(dsm);

    const int tid = threadIdx.x;

    // Supertile raster: bid -> (mt, nt); mt fastest within a GROUP_M band.
    const int bid = blockIdx.x;
    const int band = bid / (GROUP_M * TILES_N);
    const int within = bid - band * (GROUP_M * TILES_N);
    const int mt = band * GROUP_M + (within % GROUP_M);
    const int nt = within / GROUP_M;
    const int m0 = mt * BM;
    const int n0 = nt * BN;

    // Hoisted per-thread load geometry: 128 threads cover 16 rows x 8 cols of
    // 16B chunks; chunk q adds 16 rows. 8 q's each for A and B per stage.
    const int lrow = tid >> 3;              // [0,16)
    const int lcol = (tid & 7) * 8;         // halves
    const __half* gA = g_Ah + (size_t)(m0 + lrow) * K_TOT + lcol;
    const __half* gB = g_Qh + (size_t)(n0 + lrow) * K_TOT + lcol;
    __half* sAd[STAGES];
    __half* sBd[STAGES];
    #pragma unroll
    for (int s = 0; s < STAGES; ++s) {
        sAd[s] = smem_h + s * STAGE_HALVES + lrow * LDT + lcol;
        sBd[s] = smem_h + s * STAGE_HALVES + BM * LDT + lrow * LDT + lcol;
    }

    // One A-chunk + one B-chunk at offset q*16 rows.
    auto issue_q = [&](int s, const __half* A, const __half* B, int q) {
        __pipeline_memcpy_async(sAd[s] + q * (16 * LDT), A + q * (size_t)(16 * K_TOT), 16);
        __pipeline_memcpy_async(sBd[s] + q * (16 * LDT), B + q * (size_t)(16 * K_TOT), 16);
    };
    auto issue_all = [&](int s, const __half* A, const __half* B) {
        #pragma unroll
        for (int q = 0; q < 8; ++q) issue_q(s, A, B, q);
    };

    const int warpId = tid >> 5;
    const int lane   = tid & 31;
    const int wm = (warpId & 1) * 64;   // 2 warps along M
    const int wn = (warpId >> 1) * 64;  // 2 warps along N

    wmma::fragment<wmma::matrix_a, 16, 16, 16, __half, wmma::row_major> fa[4];
    wmma::fragment<wmma::matrix_b, 16, 16, 16, __half, wmma::col_major> fb[4];
    wmma::fragment<wmma::accumulator, 16, 16, 16, float> acc[4][4];
    #pragma unroll
    for (int i = 0; i < 4; ++i)
        #pragma unroll
        for (int j = 0; j < 4; ++j)
            wmma::fill_fragment(acc[i][j], 0.0f);

    // Prologue: stages 0 and 1
    issue_all(0, gA, gB);           __pipeline_commit();
    issue_all(1, gA + BK, gB + BK); __pipeline_commit();

    const __half* pfA = gA + 2 * BK;    // prefetch pointers (stage t+2)
    const __half* pfB = gB + 2 * BK;
    int sc = 0;                         // consume stage
    int sp = 2;                         // prefetch stage

    for (int t = 0; t < NT; ++t) {
        __pipeline_wait_prior((t + 1 < NT) ? 1 : 0);   // group t complete
        __syncthreads();                               // t visible; t-1 retired by all
        const __half* As = smem_h + sc * STAGE_HALVES;
        const __half* Bs = As + BM * LDT;
        const bool pre = (t + 2 < NT);
        #pragma unroll
        for (int kq = 0; kq < 4; ++kq) {
            const int kk = kq * 16;
            // Fragment loads FIRST (LSU sees LDSMs before this kk's cp.asyncs).
            #pragma unroll
            for (int i = 0; i < 4; ++i)
                wmma::load_matrix_sync(fa[i], As + (wm + i * 16) * LDT + kk, LDT);
            #pragma unroll
            for (int j = 0; j < 4; ++j)
                wmma::load_matrix_sync(fb[j], Bs + (wn + j * 16) * LDT + kk, LDT);
            // Spread next-stage copies: 2 (A,B) chunk pairs per kk.
            if (pre) {
                issue_q(sp, pfA, pfB, kq * 2);
                issue_q(sp, pfA, pfB, kq * 2 + 1);
            }
            #pragma unroll
            for (int i = 0; i < 4; ++i)
                #pragma unroll
                for (int j = 0; j < 4; ++j)
                    wmma::mma_sync(acc[i][j], fa[i], fb[j], acc[i][j]);
        }
        if (pre) __pipeline_commit();
        pfA += BK; pfB += BK;
        sc = (sc == STAGES - 1) ? 0 : sc + 1;
        sp = (sp == STAGES - 1) ? 0 : sp + 1;
    }

    // Epilogue: stage 16x16 tiles through per-warp smem; float4 path.
    __syncthreads();
    const float* scale = g_swap_sb ? sb1 : sb0;
    const float* bias  = g_swap_sb ? sb0 : sb1;
    float* cbuf = reinterpret_cast<float*>(dsm) + warpId * 256;   // 1KB/warp

    #pragma unroll
    for (int i = 0; i < 4; ++i) {
        #pragma unroll
        for (int j = 0; j < 4; ++j) {
            wmma::store_matrix_sync(cbuf, acc[i][j], 16, wmma::mem_row_major);
            __syncwarp();
            const int gm_base = m0 + wm + i * 16;
            const int gn_base = n0 + wn + j * 16;
            #pragma unroll
            for (int q = 0; q < 2; ++q) {
                const int idx = lane * 2 + q;     // 0..63 float4 slots
                const int r   = idx >> 2;         // row 0..15
                const int c4  = (idx & 3) * 4;    // col 0,4,8,12
                float4 v  = *(const float4*)(cbuf + r * 16 + c4);
                float4 sc4 = *(const float4*)(scale + gn_base + c4);
                float4 bi4 = *(const float4*)(bias + gn_base + c4);
                float4 o;
                o.x = v.x * sc4.x + bi4.x;
                o.y = v.y * sc4.y + bi4.y;
                o.z = v.z * sc4.z + bi4.z;
                o.w = v.w * sc4.w + bi4.w;
                *(float4*)(out + (size_t)(gm_base + r) * N_TOT + gn_base + c4) = o;
            }
            __syncwarp();
        }
    }
}

// ---------------------------------------------------------------------------
extern "C" void kernel_launch(void* const* d_in, const int* in_sizes, int n_in,
                              void* d_out, int out_size) {
    (void)out_size;
    // Bind by element count: x 33554432 | qweight 29360128 | scale/bias 14336
    int ix = 0, iq = 1, isb0 = 2, isb1 = 3, nsb = 0;
    int sb_idx[2] = {2, 3};
    for (int i = 0; i < n_in && i < 8; ++i) {
        if (in_sizes[i] == M_TOT * K_TOT) ix = i;
        else if (in_sizes[i] == NPACK) iq = i;
        else if (in_sizes[i] == N_TOT && nsb < 2) sb_idx[nsb++] = i;
    }
    if (nsb == 2) { isb0 = sb_idx[0]; isb1 = sb_idx[1]; }

    const float* x   = (const float*)d_in[ix];
    const void*  qw  = d_in[iq];
    const float* sb0 = (const float*)d_in[isb0];
    const float* sb1 = (const float*)d_in[isb1];
    float*       out = (float*)d_out;

    prep_kernel<<<PREP_GRID, 256>>>(x, qw, sb0);

    cudaFuncSetAttribute(gemm_f16_kernel,
                         cudaFuncAttributeMaxDynamicSharedMemorySize, SMEM_BYTES);
    gemm_f16_kernel<<<TILES_M * TILES_N, NTHREADS, SMEM_BYTES>>>(sb0, sb1, out);
}

// round 17
// speedup vs baseline: 1.5743x; 1.5743x over previous
#include <cuda_runtime.h>
#include <cuda_fp16.h>
#include <mma.h>
#include <cuda_pipeline.h>
#include <cstdint>

using namespace nvcuda;

// Problem dims
#define M_TOT 8192          // 4*2048
#define N_TOT 14336
#define K_TOT 4096
#define NPACK (N_TOT * (K_TOT / 2))

// GEMM tiling (fp16 wmma 16x16x16, single K pass)
#define BM 128
#define BN 128
#define BK 64               // 64 fp16 per stage row (128B)
#define LDT 72              // smem row stride (halves): 64 + 8 pad (16B-aligned rows)
#define NT (K_TOT / BK)     // 64 k-iterations
#define STAGES 3
#define STAGE_HALVES ((BM + BN) * LDT)              // 18432 halves = 36864 B
#define SMEM_BYTES (STAGES * STAGE_HALVES * 2)      // 110592 B dynamic (2 CTAs/SM)
#define NTHREADS 128        // 4 warps, warp tile 64x64 (2x2)

// Rasterization: supertiles of GROUP_M m-tiles (fast) x all n-tiles
#define TILES_M (M_TOT / BM)      // 64
#define TILES_N (N_TOT / BN)      // 112
#define GROUP_M 16

// Fused prep kernel geometry
#define VEC_A ((M_TOT * K_TOT) / 8)     // 4194304 conv items (8 floats each)
#define VEC_W (NPACK / 4)               // 7340032 unpack items (4 bytes each)
#define A_BLOCKS (VEC_A / 256)          // 16384
#define W_BLOCKS (VEC_W / 256)          // 28672
#define PREP_GRID (1 + A_BLOCKS + W_BLOCKS)

// Scratch (static device globals: allocation-free per harness rules)
__device__ __align__(256) __half g_Ah[(size_t)M_TOT * K_TOT];   // 67 MB: x in fp16
__device__ __align__(256) __half g_Qh[(size_t)N_TOT * K_TOT];   // 117 MB: weights fp16
__device__ int g_swap_sb;   // 1 => sb0 is actually bias

// ---------------------------------------------------------------------------
// Fused prep:
//  block 0:                 sign probe (scale strictly positive vs bias).
//  blocks [1, 1+A_BLOCKS):  x fp32 -> fp16, 8 floats -> one 16B store.
//  remaining blocks:        unpack 4-bit pairs -> fp16 in [-8,7]; each block
//                           self-detects int32-promoted qweight storage by
//                           checking the first 64 words (all in [-128,127]
//                           => promoted; impossible for packed nibble data).
// ---------------------------------------------------------------------------
__device__ __forceinline__ __half2 dec_pair(int v) {
    int hi = v >> 4;                   // arithmetic shift: even column
    int lo = ((v & 15) ^ 8) - 8;       // sign-extended low nibble: odd column
    return __floats2half2_rn((float)hi, (float)lo);
}

__global__ __launch_bounds__(256) void prep_kernel(const float* __restrict__ x,
                                                   const void* __restrict__ qw_raw,
                                                   const float* __restrict__ sb0) {
    const int bid = blockIdx.x;
    const int tid = threadIdx.x;

    if (bid == 0) {
        // Sign probe on sb0: any negative => sb0 is bias.
        int local_neg = 0;
        for (int i = tid; i < N_TOT; i += 256)
            if (sb0[i] < 0.0f) local_neg = 1;
        int any_neg = __syncthreads_or(local_neg);
        if (tid == 0) g_swap_sb = any_neg;
        return;
    }

    if (bid <= A_BLOCKS) {
        // conv_x: idx over groups of 8 floats
        int idx = (bid - 1) * 256 + tid;
        const float4* xv = (const float4*)x;
        float4 a = xv[idx * 2];
        float4 b = xv[idx * 2 + 1];
        union { __half2 h2[4]; uint4 u; } o;
        o.h2[0] = __floats2half2_rn(a.x, a.y);
        o.h2[1] = __floats2half2_rn(a.z, a.w);
        o.h2[2] = __floats2half2_rn(b.x, b.y);
        o.h2[3] = __floats2half2_rn(b.z, b.w);
        ((uint4*)g_Ah)[idx] = o.u;
        return;
    }

    // unpack: block-local dtype probe (words 0..63 are L2-hot across blocks)
    const int* qw32 = (const int*)qw_raw;
    int w0 = qw32[tid & 63];
    int bad = (w0 < -128 || w0 > 127) ? 1 : 0;
    int is_i32 = !__syncthreads_or(bad);

    int idx = (bid - 1 - A_BLOCKS) * 256 + tid;   // per 4 packed bytes
    int b0, b1, b2, b3;
    if (is_i32) {
        int4 w = ((const int4*)qw_raw)[idx];
        b0 = w.x; b1 = w.y; b2 = w.z; b3 = w.w;
    } else {
        int w = qw32[idx];
        b0 = (int)(signed char)(w);
        b1 = (int)(signed char)(w >> 8);
        b2 = (int)(signed char)(w >> 16);
        b3 = (int)(signed char)(w >> 24);
    }
    union { __half2 h2[4]; uint4 u; } o;
    o.h2[0] = dec_pair(b0);
    o.h2[1] = dec_pair(b1);
    o.h2[2] = dec_pair(b2);
    o.h2[3] = dec_pair(b3);
    ((uint4*)g_Qh)[idx] = o.u;
}

// ---------------------------------------------------------------------------
// GEMM: out[m,n] = scale[n] * sum_k Ah[m,k]*Qh[n,k] + bias[n]
// EXACT R11 champion kernel: 128x128 CTA tile, 4 warps, warp tile 64x64,
// BK=64, 3-stage cp.async (2 CTAs/SM), LDSMs first each kk, cp.asyncs
// spread 2-chunks-per-kk, hoisted pointers, scalar staged epilogue.
// ---------------------------------------------------------------------------
__global__ __launch_bounds__(NTHREADS) void gemm_f16_kernel(const float* __restrict__ sb0,
                                                            const float* __restrict__ sb1,
                                                            float* __restrict__ out) {
    extern __shared__ __align__(16) char dsm[];
    __half* smem_h = reinterpret_cast<__half*>(dsm);

    const int tid = threadIdx.x;

    // Supertile raster: bid -> (mt, nt); mt fastest within a GROUP_M band.
    const int bid = blockIdx.x;
    const int band = bid / (GROUP_M * TILES_N);
    const int within = bid - band * (GROUP_M * TILES_N);
    const int mt = band * GROUP_M + (within % GROUP_M);
    const int nt = within / GROUP_M;
    const int m0 = mt * BM;
    const int n0 = nt * BN;

    // Hoisted per-thread load geometry: 128 threads cover 16 rows x 8 cols of
    // 16B chunks; chunk q adds 16 rows. 8 q's each for A and B per stage.
    const int lrow = tid >> 3;              // [0,16)
    const int lcol = (tid & 7) * 8;         // halves
    const __half* gA = g_Ah + (size_t)(m0 + lrow) * K_TOT + lcol;
    const __half* gB = g_Qh + (size_t)(n0 + lrow) * K_TOT + lcol;
    __half* sAd[STAGES];
    __half* sBd[STAGES];
    #pragma unroll
    for (int s = 0; s < STAGES; ++s) {
        sAd[s] = smem_h + s * STAGE_HALVES + lrow * LDT + lcol;
        sBd[s] = smem_h + s * STAGE_HALVES + BM * LDT + lrow * LDT + lcol;
    }

    // One A-chunk + one B-chunk at offset q*16 rows.
    auto issue_q = [&](int s, const __half* A, const __half* B, int q) {
        __pipeline_memcpy_async(sAd[s] + q * (16 * LDT), A + q * (size_t)(16 * K_TOT), 16);
        __pipeline_memcpy_async(sBd[s] + q * (16 * LDT), B + q * (size_t)(16 * K_TOT), 16);
    };
    auto issue_all = [&](int s, const __half* A, const __half* B) {
        #pragma unroll
        for (int q = 0; q < 8; ++q) issue_q(s, A, B, q);
    };

    const int warpId = tid >> 5;
    const int lane   = tid & 31;
    const int wm = (warpId & 1) * 64;   // 2 warps along M
    const int wn = (warpId >> 1) * 64;  // 2 warps along N

    wmma::fragment<wmma::matrix_a, 16, 16, 16, __half, wmma::row_major> fa[4];
    wmma::fragment<wmma::matrix_b, 16, 16, 16, __half, wmma::col_major> fb[4];
    wmma::fragment<wmma::accumulator, 16, 16, 16, float> acc[4][4];
    #pragma unroll
    for (int i = 0; i < 4; ++i)
        #pragma unroll
        for (int j = 0; j < 4; ++j)
            wmma::fill_fragment(acc[i][j], 0.0f);

    // Prologue: stages 0 and 1
    issue_all(0, gA, gB);           __pipeline_commit();
    issue_all(1, gA + BK, gB + BK); __pipeline_commit();

    const __half* pfA = gA + 2 * BK;    // prefetch pointers (stage t+2)
    const __half* pfB = gB + 2 * BK;
    int sc = 0;                         // consume stage
    int sp = 2;                         // prefetch stage

    for (int t = 0; t < NT; ++t) {
        __pipeline_wait_prior((t + 1 < NT) ? 1 : 0);   // group t complete
        __syncthreads();                               // t visible; t-1 retired by all
        const __half* As = smem_h + sc * STAGE_HALVES;
        const __half* Bs = As + BM * LDT;
        const bool pre = (t + 2 < NT);
        #pragma unroll
        for (int kq = 0; kq < 4; ++kq) {
            const int kk = kq * 16;
            // Fragment loads FIRST (LSU sees LDSMs before this kk's cp.asyncs).
            #pragma unroll
            for (int i = 0; i < 4; ++i)
                wmma::load_matrix_sync(fa[i], As + (wm + i * 16) * LDT + kk, LDT);
            #pragma unroll
            for (int j = 0; j < 4; ++j)
                wmma::load_matrix_sync(fb[j], Bs + (wn + j * 16) * LDT + kk, LDT);
            // Spread next-stage copies: 2 (A,B) chunk pairs per kk.
            if (pre) {
                issue_q(sp, pfA, pfB, kq * 2);
                issue_q(sp, pfA, pfB, kq * 2 + 1);
            }
            #pragma unroll
            for (int i = 0; i < 4; ++i)
                #pragma unroll
                for (int j = 0; j < 4; ++j)
                    wmma::mma_sync(acc[i][j], fa[i], fb[j], acc[i][j]);
        }
        if (pre) __pipeline_commit();
        pfA += BK; pfB += BK;
        sc = (sc == STAGES - 1) ? 0 : sc + 1;
        sp = (sp == STAGES - 1) ? 0 : sp + 1;
    }

    // Epilogue: stage 16x16 tiles through per-warp smem, fuse scale/bias.
    __syncthreads();
    const float* scale = g_swap_sb ? sb1 : sb0;
    const float* bias  = g_swap_sb ? sb0 : sb1;
    float* cbuf = reinterpret_cast<float*>(dsm) + warpId * 256;   // 1KB/warp

    #pragma unroll
    for (int i = 0; i < 4; ++i) {
        #pragma unroll
        for (int j = 0; j < 4; ++j) {
            wmma::store_matrix_sync(cbuf, acc[i][j], 16, wmma::mem_row_major);
            __syncwarp();
            const int gm_base = m0 + wm + i * 16;
            const int gn_base = n0 + wn + j * 16;
            #pragma unroll
            for (int e = lane; e < 256; e += 32) {
                int r = e >> 4, c = e & 15;
                int gn = gn_base + c;
                out[(size_t)(gm_base + r) * N_TOT + gn] = cbuf[e] * scale[gn] + bias[gn];
            }
            __syncwarp();
        }
    }
}

// ---------------------------------------------------------------------------
extern "C" void kernel_launch(void* const* d_in, const int* in_sizes, int n_in,
                              void* d_out, int out_size) {
    (void)out_size;
    // Bind by element count: x 33554432 | qweight 29360128 | scale/bias 14336
    int ix = 0, iq = 1, isb0 = 2, isb1 = 3, nsb = 0;
    int sb_idx[2] = {2, 3};
    for (int i = 0; i < n_in && i < 8; ++i) {
        if (in_sizes[i] == M_TOT * K_TOT) ix = i;
        else if (in_sizes[i] == NPACK) iq = i;
        else if (in_sizes[i] == N_TOT && nsb < 2) sb_idx[nsb++] = i;
    }
    if (nsb == 2) { isb0 = sb_idx[0]; isb1 = sb_idx[1]; }

    const float* x   = (const float*)d_in[ix];
    const void*  qw  = d_in[iq];
    const float* sb0 = (const float*)d_in[isb0];
    const float* sb1 = (const float*)d_in[isb1];
    float*       out = (float*)d_out;

    prep_kernel<<<PREP_GRID, 256>>>(x, qw, sb0);

    cudaFuncSetAttribute(gemm_f16_kernel,
                         cudaFuncAttributeMaxDynamicSharedMemorySize, SMEM_BYTES);
    gemm_f16_kernel<<<TILES_M * TILES_N, NTHREADS, SMEM_BYTES>>>(sb0, sb1, out);
}